// round 15
// baseline (speedup 1.0000x reference)
#include <cuda_runtime.h>
#include <cuda_fp16.h>
#include <cstdint>

#define N       8192
#define SPLIT   9
#define NJT     64              // total j tiles
#define XSTRIDE 72              // sB row stride (halves): 64 + 8 pad
#define ZSTRIDE 24              // z tile row stride (halves): 16 + 8 pad

// ---------------- scratch (no allocs allowed) ----------------
__device__ __half g_x16[N * 64];        // [r][0..59]=x, [60]=1, [61..63]=0
__device__ __half g_zh[N * 16];         // z hi (fp16)
__device__ float  g_tq[N];              // temp*log2e*||z||^2
__device__ float  g_W[976];             // W21 (16x60) + b21 (16)
__device__ float  g_part[SPLIT * N * 64];

// ---------------- helpers ----------------
static __device__ __forceinline__ uint32_t smem_u32(const void* p) {
    uint32_t a;
    asm("{ .reg .u64 t; cvta.to.shared.u64 t, %1; cvt.u32.u64 %0, t; }" : "=r"(a) : "l"(p));
    return a;
}
static __device__ __forceinline__ void mma16816(float c[4], const uint32_t a[4],
                                                uint32_t b0, uint32_t b1) {
    asm volatile(
        "mma.sync.aligned.m16n8k16.row.col.f32.f16.f16.f32 "
        "{%0,%1,%2,%3}, {%4,%5,%6,%7}, {%8,%9}, {%0,%1,%2,%3};"
        : "+f"(c[0]), "+f"(c[1]), "+f"(c[2]), "+f"(c[3])
        : "r"(a[0]), "r"(a[1]), "r"(a[2]), "r"(a[3]), "r"(b0), "r"(b1));
}
static __device__ __forceinline__ void ldsm_x2(uint32_t r[2], uint32_t addr) {
    asm volatile("ldmatrix.sync.aligned.m8n8.x2.shared.b16 {%0,%1}, [%2];"
                 : "=r"(r[0]), "=r"(r[1]) : "r"(addr));
}
static __device__ __forceinline__ void ldsm_x4_t(uint32_t r[4], uint32_t addr) {
    asm volatile("ldmatrix.sync.aligned.m8n8.x4.trans.shared.b16 {%0,%1,%2,%3}, [%4];"
                 : "=r"(r[0]), "=r"(r[1]), "=r"(r[2]), "=r"(r[3]) : "r"(addr));
}
static __device__ __forceinline__ uint32_t ld32g(const __half* p) {
    return *reinterpret_cast<const uint32_t*>(p);
}
static __device__ __forceinline__ uint32_t h2bits(__half2 v) {
    return *reinterpret_cast<uint32_t*>(&v);
}

// ================= k0: fold fc1/fc2 -> W21 (16x60), b21 =================
__global__ __launch_bounds__(128) void k0_fold(
    const float* __restrict__ w1, const float* __restrict__ b1,
    const float* __restrict__ w2, const float* __restrict__ b2)
{
    __shared__ float sw1[32 * 60], sw2[16 * 32], sb1[32];
    int tid = threadIdx.x;
    for (int i = tid; i < 32 * 60; i += 128) sw1[i] = w1[i];
    for (int i = tid; i < 16 * 32; i += 128) sw2[i] = w2[i];
    if (tid < 32) sb1[tid] = b1[tid];
    __syncthreads();
    for (int e = tid; e < 960; e += 128) {
        int o = e / 60, k = e % 60;
        float s = 0.f;
#pragma unroll
        for (int m = 0; m < 32; m++) s = fmaf(sw2[o * 32 + m], sw1[m * 60 + k], s);
        g_W[e] = s;
    }
    if (tid < 16) {
        float s = b2[tid];
#pragma unroll
        for (int m = 0; m < 32; m++) s = fmaf(sw2[tid * 32 + m], sb1[m], s);
        g_W[960 + tid] = s;
    }
}

// ================= k1: z = W21 x + b21, zh, x fp16, tq =================
// 256 thr/block, 64 rows/block (4 thr/row, 4 z-outputs each), grid 128.
__global__ __launch_bounds__(256) void k1_embed(
    const float* __restrict__ x,
    const float* __restrict__ temp_p)
{
    __shared__ __align__(16) float sx[64 * 60];
    __shared__ __align__(16) float sWb[976];
    int tid = threadIdx.x;
    int rows0 = blockIdx.x * 64;

    for (int e = tid; e < 3840; e += 256) sx[e] = x[(size_t)rows0 * 60 + e];
    for (int e = tid; e < 976; e += 256) sWb[e] = g_W[e];
    __syncthreads();

    int r = tid >> 2, s = tid & 3;
    const float* xr = sx + r * 60;
    const float* w0p = sWb + (4 * s + 0) * 60;
    const float* w1p = sWb + (4 * s + 1) * 60;
    const float* w2p = sWb + (4 * s + 2) * 60;
    const float* w3p = sWb + (4 * s + 3) * 60;

    float z0 = sWb[960 + 4 * s + 0];
    float z1 = sWb[960 + 4 * s + 1];
    float z2 = sWb[960 + 4 * s + 2];
    float z3 = sWb[960 + 4 * s + 3];
#pragma unroll
    for (int q = 0; q < 15; q++) {
        float4 xa = *(const float4*)(xr + 4 * q);
        float4 a = *(const float4*)(w0p + 4 * q);
        float4 b = *(const float4*)(w1p + 4 * q);
        float4 c = *(const float4*)(w2p + 4 * q);
        float4 d = *(const float4*)(w3p + 4 * q);
        z0 = fmaf(a.x, xa.x, z0); z1 = fmaf(b.x, xa.x, z1);
        z2 = fmaf(c.x, xa.x, z2); z3 = fmaf(d.x, xa.x, z3);
        z0 = fmaf(a.y, xa.y, z0); z1 = fmaf(b.y, xa.y, z1);
        z2 = fmaf(c.y, xa.y, z2); z3 = fmaf(d.y, xa.y, z3);
        z0 = fmaf(a.z, xa.z, z0); z1 = fmaf(b.z, xa.z, z1);
        z2 = fmaf(c.z, xa.z, z2); z3 = fmaf(d.z, xa.z, z3);
        z0 = fmaf(a.w, xa.w, z0); z1 = fmaf(b.w, xa.w, z1);
        z2 = fmaf(c.w, xa.w, z2); z3 = fmaf(d.w, xa.w, z3);
    }

    float sq = fmaf(z0, z0, fmaf(z1, z1, fmaf(z2, z2, z3 * z3)));
    sq += __shfl_xor_sync(0xffffffffu, sq, 1);
    sq += __shfl_xor_sync(0xffffffffu, sq, 2);

    int R = rows0 + r;
    if (s == 0) g_tq[R] = (*temp_p) * 1.4426950408889634f * sq;

    {
        __half2 p0 = __halves2half2(__float2half_rn(z0), __float2half_rn(z1));
        __half2 p1 = __halves2half2(__float2half_rn(z2), __float2half_rn(z3));
        uint2 v = make_uint2(h2bits(p0), h2bits(p1));
        *(uint2*)(g_zh + (size_t)R * 16 + 4 * s) = v;
    }

    union { __half h[16]; uint4 v[2]; } xo;
    if (s < 3) {
#pragma unroll
        for (int f = 0; f < 16; f++) xo.h[f] = __float2half_rn(xr[16 * s + f]);
    } else {
#pragma unroll
        for (int f = 0; f < 12; f++) xo.h[f] = __float2half_rn(xr[48 + f]);
        xo.h[12] = __float2half_rn(1.0f);
        xo.h[13] = __float2half_rn(0.0f);
        xo.h[14] = __float2half_rn(0.0f);
        xo.h[15] = __float2half_rn(0.0f);
    }
    uint4* xd = (uint4*)(g_x16 + (size_t)R * 64 + 16 * s);
    xd[0] = xo.v[0];
    xd[1] = xo.v[1];
}

// ---------------- k2 per-tile body ----------------
// w = L2E*(theta - temp*dist) = pS*S + (thL - tq_i) - tq_j ; A = e/(1+e), e = 2^w
template <bool DIAG>
static __device__ __forceinline__ void k2_tile(
    uint32_t pvBase, uint32_t zhBase, const float* stq,
    const uint32_t aih[2][4], const float rc[2][2],
    float pS, int wid, int g, int t, float C[2][8][4])
{
    const __half2 ones = __floats2half2_rn(1.f, 1.f);
    const __half  oneh = __float2half(1.f);
#pragma unroll
    for (int ks = 0; ks < 8; ks++) {
        float2 tqa = *(const float2*)(stq + ks * 16 + 2 * t);
        float2 tqb = *(const float2*)(stq + ks * 16 + 8 + 2 * t);
        uint32_t zh0[2], zh1[2];
        ldsm_x2(zh0, zhBase + (ks * 16 + 0) * (ZSTRIDE * 2));
        ldsm_x2(zh1, zhBase + (ks * 16 + 8) * (ZSTRIDE * 2));

        // hoisted PV B fragments: depend only on (ks, p) — shared across rg
        uint32_t bb[4][4];
#pragma unroll
        for (int p = 0; p < 4; p++)
            ldsm_x4_t(bb[p], pvBase + ks * (16 * XSTRIDE * 2) + p * 32);

#pragma unroll
        for (int rg = 0; rg < 2; rg++) {
            float S0[4] = {0.f, 0.f, 0.f, 0.f};
            float S1[4] = {0.f, 0.f, 0.f, 0.f};
            mma16816(S0, aih[rg], zh0[0], zh0[1]);
            mma16816(S1, aih[rg], zh1[0], zh1[1]);

            const float rA = rc[rg][0], rB = rc[rg][1];
            __half2 wA0 = __floats2half2_rn(fmaf(pS, S0[0], rA) - tqa.x,
                                            fmaf(pS, S0[1], rA) - tqa.y);
            __half2 wB0 = __floats2half2_rn(fmaf(pS, S0[2], rB) - tqa.x,
                                            fmaf(pS, S0[3], rB) - tqa.y);
            __half2 wA1 = __floats2half2_rn(fmaf(pS, S1[0], rA) - tqb.x,
                                            fmaf(pS, S1[1], rA) - tqb.y);
            __half2 wB1 = __floats2half2_rn(fmaf(pS, S1[2], rB) - tqb.x,
                                            fmaf(pS, S1[3], rB) - tqb.y);
            __half2 eA0 = h2exp2(wA0), eB0 = h2exp2(wB0);
            __half2 eA1 = h2exp2(wA1), eB1 = h2exp2(wB1);
            __half2 AA0 = __hmul2(eA0, h2rcp(__hadd2(ones, eA0)));
            __half2 AB0 = __hmul2(eB0, h2rcp(__hadd2(ones, eB0)));
            __half2 AA1 = __hmul2(eA1, h2rcp(__hadd2(ones, eA1)));
            __half2 AB1 = __hmul2(eB1, h2rcp(__hadd2(ones, eB1)));

            if (DIAG) {
                int rAl = wid * 32 + rg * 16 + g;
                int rBl = rAl + 8;
                int c0 = ks * 16 + 2 * t;
                if (c0     == rAl) AA0 = __halves2half2(oneh, __high2half(AA0));
                if (c0 + 1 == rAl) AA0 = __halves2half2(__low2half(AA0), oneh);
                if (c0     == rBl) AB0 = __halves2half2(oneh, __high2half(AB0));
                if (c0 + 1 == rBl) AB0 = __halves2half2(__low2half(AB0), oneh);
                if (c0 + 8 == rAl) AA1 = __halves2half2(oneh, __high2half(AA1));
                if (c0 + 9 == rAl) AA1 = __halves2half2(__low2half(AA1), oneh);
                if (c0 + 8 == rBl) AB1 = __halves2half2(oneh, __high2half(AB1));
                if (c0 + 9 == rBl) AB1 = __halves2half2(__low2half(AB1), oneh);
            }

            uint32_t a[4];
            a[0] = h2bits(AA0);
            a[1] = h2bits(AB0);
            a[2] = h2bits(AA1);
            a[3] = h2bits(AB1);

#pragma unroll
            for (int p = 0; p < 4; p++) {
                mma16816(C[rg][2 * p],     a, bb[p][0], bb[p][1]);
                mma16816(C[rg][2 * p + 1], a, bb[p][2], bb[p][3]);
            }
        }
    }
}

// ================= k2: S-MMA + f16x2 sigmoid + PV-MMA =================
// grid (64 i-tiles, SPLIT=9 j-splits of 7-8 tiles) = 576 CTAs (balance fix).
__global__ __launch_bounds__(128) void k2_aggregate(
    const float* __restrict__ temp_p,
    const float* __restrict__ theta_p)
{
    __shared__ __align__(16) __half sB[128 * XSTRIDE];
    __shared__ __align__(16) __half szh[128 * ZSTRIDE];
    __shared__ float stq[128];

    const int tid  = threadIdx.x;
    const int wid  = tid >> 5;
    const int lane = tid & 31;
    const int g = lane >> 2;
    const int t = lane & 3;

    const int rowBase = blockIdx.x * 128;
    const int t0 = (blockIdx.y * NJT) / SPLIT;
    const int t1 = ((blockIdx.y + 1) * NJT) / SPLIT;

    const float L2E  = 1.4426950408889634f;
    const float temp = *temp_p;
    const float thL  = (*theta_p) * L2E;
    const float pS   = 2.f * temp * L2E;

    uint32_t aih[2][4];
    float rc[2][2];
#pragma unroll
    for (int rg = 0; rg < 2; rg++) {
        int R  = rowBase + wid * 32 + rg * 16;
        int rA = R + g, rB = R + g + 8;
        aih[rg][0] = ld32g(g_zh + (size_t)rA * 16 + 2 * t);
        aih[rg][1] = ld32g(g_zh + (size_t)rB * 16 + 2 * t);
        aih[rg][2] = ld32g(g_zh + (size_t)rA * 16 + 2 * t + 8);
        aih[rg][3] = ld32g(g_zh + (size_t)rB * 16 + 2 * t + 8);
        rc[rg][0] = thL - g_tq[rA];
        rc[rg][1] = thL - g_tq[rB];
    }

    float C[2][8][4];
#pragma unroll
    for (int rg = 0; rg < 2; rg++)
#pragma unroll
        for (int nt = 0; nt < 8; nt++)
#pragma unroll
            for (int c = 0; c < 4; c++) C[rg][nt][c] = 0.f;

    const int lr = lane & 7;
    const int m4 = lane >> 3;
    const uint32_t pvBase = smem_u32(sB) +
        2 * (((m4 & 1) * 8 + lr) * XSTRIDE + (m4 >> 1) * 8);
    const int lz = lane & 15;
    const uint32_t zhBase = smem_u32(szh) +
        2 * ((lz & 7) * ZSTRIDE + ((lz >> 3) & 1) * 8);

    for (int tl = t0; tl < t1; ++tl) {
        const int jbase = tl * 128;
        __syncthreads();
        {
            const uint4* xs = (const uint4*)(g_x16 + (size_t)(jbase + tid) * 64);
            uint4* xd = (uint4*)(sB + tid * XSTRIDE);
#pragma unroll
            for (int q = 0; q < 8; q++) xd[q] = xs[q];
            const uint4* hs = (const uint4*)(g_zh + (size_t)(jbase + tid) * 16);
            uint4* hd = (uint4*)(szh + tid * ZSTRIDE);
            hd[0] = hs[0]; hd[1] = hs[1];
            stq[tid] = g_tq[jbase + tid];
        }
        __syncthreads();

        if (jbase == rowBase)
            k2_tile<true >(pvBase, zhBase, stq, aih, rc, pS, wid, g, t, C);
        else
            k2_tile<false>(pvBase, zhBase, stq, aih, rc, pS, wid, g, t, C);
    }

#pragma unroll
    for (int rg = 0; rg < 2; rg++) {
        int rA = rowBase + wid * 32 + rg * 16 + g;
        float* b0 = g_part + ((size_t)blockIdx.y * N + rA) * 64;
        float* b1 = b0 + (size_t)8 * 64;
#pragma unroll
        for (int nt = 0; nt < 8; nt++) {
            int col = nt * 8 + 2 * t;
            *(float2*)(b0 + col) = make_float2(C[rg][nt][0], C[rg][nt][1]);
            *(float2*)(b1 + col) = make_float2(C[rg][nt][2], C[rg][nt][3]);
        }
    }
}

// ================= k3: batched reduce -> normalize -> fc3 -> fc6 -> softmax =================
// 512 thr/block, 8 threads per row, 64 rows/block, grid 128. All loads batched into regs.
__global__ __launch_bounds__(512) void k3_head(
    const float* __restrict__ w3, const float* __restrict__ b3,
    const float* __restrict__ w6, const float* __restrict__ b6,
    float* __restrict__ out)
{
    __shared__ float sw3[8 * 64];   // padded: cols 60..63 = 0
    __shared__ float sb3[8], sw6[10 * 8], sb6[10];
    int tid = threadIdx.x;
    if (tid < 8 * 64) {
        int o = tid >> 6, k = tid & 63;
        sw3[tid] = (k < 60) ? w3[o * 60 + k] : 0.f;
    }
    if (tid < 8)  sb3[tid] = b3[tid];
    else if (tid >= 32 && tid < 112) sw6[tid - 32] = w6[tid - 32];
    else if (tid >= 128 && tid < 138) sb6[tid - 128] = b6[tid - 128];
    __syncthreads();

    const int rloc = tid >> 3, sub = tid & 7;
    const int r = blockIdx.x * 64 + rloc;

    // batch ALL partial loads into registers first (full MLP)
    float4 v[2 * SPLIT];
#pragma unroll
    for (int s = 0; s < SPLIT; s++) {
        const float4* p = (const float4*)(g_part + ((size_t)s * N + r) * 64 + sub * 8);
        v[2 * s]     = p[0];
        v[2 * s + 1] = p[1];
    }

    float acc[8];
#pragma unroll
    for (int k = 0; k < 8; k++) acc[k] = 0.f;
#pragma unroll
    for (int s = 0; s < SPLIT; s++) {
        acc[0] += v[2 * s].x;     acc[1] += v[2 * s].y;
        acc[2] += v[2 * s].z;     acc[3] += v[2 * s].w;
        acc[4] += v[2 * s + 1].x; acc[5] += v[2 * s + 1].y;
        acc[6] += v[2 * s + 1].z; acc[7] += v[2 * s + 1].w;
    }

    const unsigned fullm = 0xffffffffu;
    float rs = __shfl_sync(fullm, acc[4], (tid & 31) | 7);   // col 60
    float inv = 1.f / rs;
#pragma unroll
    for (int k = 0; k < 8; k++) acc[k] *= inv;

    float p8[8];
#pragma unroll
    for (int o = 0; o < 8; o++) {
        const float* wrow = sw3 + o * 64 + sub * 8;
        float s = 0.f;
#pragma unroll
        for (int k = 0; k < 8; k++) s = fmaf(wrow[k], acc[k], s);
        p8[o] = s;
    }
#pragma unroll
    for (int d = 1; d < 8; d <<= 1)
#pragma unroll
        for (int o = 0; o < 8; o++) p8[o] += __shfl_xor_sync(fullm, p8[o], d);

    float tv[8];
#pragma unroll
    for (int o = 0; o < 8; o++) tv[o] = p8[o] + sb3[o];

    float u[10];
    float m = -1e30f;
#pragma unroll
    for (int c = 0; c < 10; c++) {
        float s = sb6[c];
#pragma unroll
        for (int o = 0; o < 8; o++) s = fmaf(sw6[c * 8 + o], tv[o], s);
        u[c] = s;
        m = fmaxf(m, s);
    }
    float denom = 0.f;
#pragma unroll
    for (int c = 0; c < 10; c++) { u[c] = __expf(u[c] - m); denom += u[c]; }
    float dinv = 1.f / denom;
    if (sub == 0) {
#pragma unroll
        for (int c = 0; c < 10; c++) out[(size_t)r * 10 + c] = u[c] * dinv;
    }
}

// ================= launch =================
extern "C" void kernel_launch(void* const* d_in, const int* in_sizes, int n_in,
                              void* d_out, int out_size)
{
    const float* x     = (const float*)d_in[0];
    const float* w1    = (const float*)d_in[1];
    const float* b1    = (const float*)d_in[2];
    const float* w2    = (const float*)d_in[3];
    const float* b2    = (const float*)d_in[4];
    const float* w3    = (const float*)d_in[5];
    const float* b3    = (const float*)d_in[6];
    const float* w6    = (const float*)d_in[7];
    const float* b6    = (const float*)d_in[8];
    const float* temp  = (const float*)d_in[9];
    const float* theta = (const float*)d_in[10];
    float* out = (float*)d_out;

    k0_fold<<<1, 128>>>(w1, b1, w2, b2);
    k1_embed<<<N / 64, 256>>>(x, temp);
    dim3 g2(N / 128, SPLIT);
    k2_aggregate<<<g2, 128>>>(temp, theta);
    k3_head<<<N / 64, 512>>>(w3, b3, w6, b6, out);
}

// round 16
// speedup vs baseline: 1.0839x; 1.0839x over previous
#include <cuda_runtime.h>
#include <cuda_fp16.h>
#include <cstdint>

#define N       8192
#define SPLIT   8
#define JCHUNK  (N / SPLIT)     // 1024
#define TILES   (JCHUNK / 128)  // 8
#define XSTRIDE 72              // sB row stride (halves): 64 + 8 pad
#define ZSTRIDE 24              // z tile row stride (halves): 16 + 8 pad

// ---------------- scratch (no allocs allowed) ----------------
__device__ __half g_x16[N * 64];        // [r][0..59]=x, [60]=1, [61..63]=0
__device__ __half g_zh[N * 16];         // z hi (fp16)
__device__ float  g_tq[N];              // temp*log2e*||z||^2
__device__ float  g_W[976];             // W21 (16x60) + b21 (16)
__device__ float  g_part[SPLIT * N * 64];

// ---------------- helpers ----------------
static __device__ __forceinline__ uint32_t smem_u32(const void* p) {
    uint32_t a;
    asm("{ .reg .u64 t; cvta.to.shared.u64 t, %1; cvt.u32.u64 %0, t; }" : "=r"(a) : "l"(p));
    return a;
}
static __device__ __forceinline__ void mma16816(float c[4], const uint32_t a[4],
                                                uint32_t b0, uint32_t b1) {
    asm volatile(
        "mma.sync.aligned.m16n8k16.row.col.f32.f16.f16.f32 "
        "{%0,%1,%2,%3}, {%4,%5,%6,%7}, {%8,%9}, {%0,%1,%2,%3};"
        : "+f"(c[0]), "+f"(c[1]), "+f"(c[2]), "+f"(c[3])
        : "r"(a[0]), "r"(a[1]), "r"(a[2]), "r"(a[3]), "r"(b0), "r"(b1));
}
static __device__ __forceinline__ void ldsm_x4(uint32_t r[4], uint32_t addr) {
    asm volatile("ldmatrix.sync.aligned.m8n8.x4.shared.b16 {%0,%1,%2,%3}, [%4];"
                 : "=r"(r[0]), "=r"(r[1]), "=r"(r[2]), "=r"(r[3]) : "r"(addr));
}
static __device__ __forceinline__ void ldsm_x4_t(uint32_t r[4], uint32_t addr) {
    asm volatile("ldmatrix.sync.aligned.m8n8.x4.trans.shared.b16 {%0,%1,%2,%3}, [%4];"
                 : "=r"(r[0]), "=r"(r[1]), "=r"(r[2]), "=r"(r[3]) : "r"(addr));
}
static __device__ __forceinline__ uint32_t ld32g(const __half* p) {
    return *reinterpret_cast<const uint32_t*>(p);
}
static __device__ __forceinline__ uint32_t h2bits(__half2 v) {
    return *reinterpret_cast<uint32_t*>(&v);
}

// ================= k0: fold fc1/fc2 -> W21 (16x60), b21 =================
__global__ __launch_bounds__(128) void k0_fold(
    const float* __restrict__ w1, const float* __restrict__ b1,
    const float* __restrict__ w2, const float* __restrict__ b2)
{
    __shared__ float sw1[32 * 60], sw2[16 * 32], sb1[32];
    int tid = threadIdx.x;
    for (int i = tid; i < 32 * 60; i += 128) sw1[i] = w1[i];
    for (int i = tid; i < 16 * 32; i += 128) sw2[i] = w2[i];
    if (tid < 32) sb1[tid] = b1[tid];
    __syncthreads();
    for (int e = tid; e < 960; e += 128) {
        int o = e / 60, k = e % 60;
        float s = 0.f;
#pragma unroll
        for (int m = 0; m < 32; m++) s = fmaf(sw2[o * 32 + m], sw1[m * 60 + k], s);
        g_W[e] = s;
    }
    if (tid < 16) {
        float s = b2[tid];
#pragma unroll
        for (int m = 0; m < 32; m++) s = fmaf(sw2[tid * 32 + m], sb1[m], s);
        g_W[960 + tid] = s;
    }
}

// ================= k1: z = W21 x + b21, zh, x fp16, tq =================
// 256 thr/block, 64 rows/block (4 thr/row, 4 z-outputs each), grid 128.
__global__ __launch_bounds__(256) void k1_embed(
    const float* __restrict__ x,
    const float* __restrict__ temp_p)
{
    __shared__ __align__(16) float sx[64 * 60];
    __shared__ __align__(16) float sWb[976];
    int tid = threadIdx.x;
    int rows0 = blockIdx.x * 64;

    for (int e = tid; e < 3840; e += 256) sx[e] = x[(size_t)rows0 * 60 + e];
    for (int e = tid; e < 976; e += 256) sWb[e] = g_W[e];
    __syncthreads();

    int r = tid >> 2, s = tid & 3;
    const float* xr = sx + r * 60;
    const float* w0p = sWb + (4 * s + 0) * 60;
    const float* w1p = sWb + (4 * s + 1) * 60;
    const float* w2p = sWb + (4 * s + 2) * 60;
    const float* w3p = sWb + (4 * s + 3) * 60;

    float z0 = sWb[960 + 4 * s + 0];
    float z1 = sWb[960 + 4 * s + 1];
    float z2 = sWb[960 + 4 * s + 2];
    float z3 = sWb[960 + 4 * s + 3];
#pragma unroll
    for (int q = 0; q < 15; q++) {
        float4 xa = *(const float4*)(xr + 4 * q);
        float4 a = *(const float4*)(w0p + 4 * q);
        float4 b = *(const float4*)(w1p + 4 * q);
        float4 c = *(const float4*)(w2p + 4 * q);
        float4 d = *(const float4*)(w3p + 4 * q);
        z0 = fmaf(a.x, xa.x, z0); z1 = fmaf(b.x, xa.x, z1);
        z2 = fmaf(c.x, xa.x, z2); z3 = fmaf(d.x, xa.x, z3);
        z0 = fmaf(a.y, xa.y, z0); z1 = fmaf(b.y, xa.y, z1);
        z2 = fmaf(c.y, xa.y, z2); z3 = fmaf(d.y, xa.y, z3);
        z0 = fmaf(a.z, xa.z, z0); z1 = fmaf(b.z, xa.z, z1);
        z2 = fmaf(c.z, xa.z, z2); z3 = fmaf(d.z, xa.z, z3);
        z0 = fmaf(a.w, xa.w, z0); z1 = fmaf(b.w, xa.w, z1);
        z2 = fmaf(c.w, xa.w, z2); z3 = fmaf(d.w, xa.w, z3);
    }

    float sq = fmaf(z0, z0, fmaf(z1, z1, fmaf(z2, z2, z3 * z3)));
    sq += __shfl_xor_sync(0xffffffffu, sq, 1);
    sq += __shfl_xor_sync(0xffffffffu, sq, 2);

    int R = rows0 + r;
    if (s == 0) g_tq[R] = (*temp_p) * 1.4426950408889634f * sq;

    {
        __half2 p0 = __halves2half2(__float2half_rn(z0), __float2half_rn(z1));
        __half2 p1 = __halves2half2(__float2half_rn(z2), __float2half_rn(z3));
        uint2 v = make_uint2(h2bits(p0), h2bits(p1));
        *(uint2*)(g_zh + (size_t)R * 16 + 4 * s) = v;
    }

    union { __half h[16]; uint4 v[2]; } xo;
    if (s < 3) {
#pragma unroll
        for (int f = 0; f < 16; f++) xo.h[f] = __float2half_rn(xr[16 * s + f]);
    } else {
#pragma unroll
        for (int f = 0; f < 12; f++) xo.h[f] = __float2half_rn(xr[48 + f]);
        xo.h[12] = __float2half_rn(1.0f);
        xo.h[13] = __float2half_rn(0.0f);
        xo.h[14] = __float2half_rn(0.0f);
        xo.h[15] = __float2half_rn(0.0f);
    }
    uint4* xd = (uint4*)(g_x16 + (size_t)R * 64 + 16 * s);
    xd[0] = xo.v[0];
    xd[1] = xo.v[1];
}

// ---------------- k2 per-tile body ----------------
// w = L2E*(theta - temp*dist) = pS*S + (thL - tq_i) - tq_j ; A = e/(1+e), e = 2^w
template <bool DIAG>
static __device__ __forceinline__ void k2_tile(
    uint32_t pvBase, uint32_t zhBase, const float* stq,
    const uint32_t aih[2][4], const float rc[2][2],
    float pS, int wid, int g, int t, float C[2][8][4])
{
    const __half2 ones = __floats2half2_rn(1.f, 1.f);
    const __half  oneh = __float2half(1.f);
#pragma unroll
    for (int ks = 0; ks < 8; ks++) {
        float2 tqa = *(const float2*)(stq + ks * 16 + 2 * t);
        float2 tqb = *(const float2*)(stq + ks * 16 + 8 + 2 * t);
        // merged z-side load: one x4 fetches zh0[0],zh0[1],zh1[0],zh1[1]
        uint32_t zz[4];
        ldsm_x4(zz, zhBase + ks * (16 * ZSTRIDE * 2));

        // hoisted PV B fragments: depend only on (ks, p) — shared across rg
        uint32_t bb[4][4];
#pragma unroll
        for (int p = 0; p < 4; p++)
            ldsm_x4_t(bb[p], pvBase + ks * (16 * XSTRIDE * 2) + p * 32);

#pragma unroll
        for (int rg = 0; rg < 2; rg++) {
            float S0[4] = {0.f, 0.f, 0.f, 0.f};
            float S1[4] = {0.f, 0.f, 0.f, 0.f};
            mma16816(S0, aih[rg], zz[0], zz[1]);
            mma16816(S1, aih[rg], zz[2], zz[3]);

            const float rA = rc[rg][0], rB = rc[rg][1];
            __half2 wA0 = __floats2half2_rn(fmaf(pS, S0[0], rA) - tqa.x,
                                            fmaf(pS, S0[1], rA) - tqa.y);
            __half2 wB0 = __floats2half2_rn(fmaf(pS, S0[2], rB) - tqa.x,
                                            fmaf(pS, S0[3], rB) - tqa.y);
            __half2 wA1 = __floats2half2_rn(fmaf(pS, S1[0], rA) - tqb.x,
                                            fmaf(pS, S1[1], rA) - tqb.y);
            __half2 wB1 = __floats2half2_rn(fmaf(pS, S1[2], rB) - tqb.x,
                                            fmaf(pS, S1[3], rB) - tqb.y);
            __half2 eA0 = h2exp2(wA0), eB0 = h2exp2(wB0);
            __half2 eA1 = h2exp2(wA1), eB1 = h2exp2(wB1);
            __half2 AA0 = __hmul2(eA0, h2rcp(__hadd2(ones, eA0)));
            __half2 AB0 = __hmul2(eB0, h2rcp(__hadd2(ones, eB0)));
            __half2 AA1 = __hmul2(eA1, h2rcp(__hadd2(ones, eA1)));
            __half2 AB1 = __hmul2(eB1, h2rcp(__hadd2(ones, eB1)));

            if (DIAG) {
                int rAl = wid * 32 + rg * 16 + g;
                int rBl = rAl + 8;
                int c0 = ks * 16 + 2 * t;
                if (c0     == rAl) AA0 = __halves2half2(oneh, __high2half(AA0));
                if (c0 + 1 == rAl) AA0 = __halves2half2(__low2half(AA0), oneh);
                if (c0     == rBl) AB0 = __halves2half2(oneh, __high2half(AB0));
                if (c0 + 1 == rBl) AB0 = __halves2half2(__low2half(AB0), oneh);
                if (c0 + 8 == rAl) AA1 = __halves2half2(oneh, __high2half(AA1));
                if (c0 + 9 == rAl) AA1 = __halves2half2(__low2half(AA1), oneh);
                if (c0 + 8 == rBl) AB1 = __halves2half2(oneh, __high2half(AB1));
                if (c0 + 9 == rBl) AB1 = __halves2half2(__low2half(AB1), oneh);
            }

            uint32_t a[4];
            a[0] = h2bits(AA0);
            a[1] = h2bits(AB0);
            a[2] = h2bits(AA1);
            a[3] = h2bits(AB1);

#pragma unroll
            for (int p = 0; p < 4; p++) {
                mma16816(C[rg][2 * p],     a, bb[p][0], bb[p][1]);
                mma16816(C[rg][2 * p + 1], a, bb[p][2], bb[p][3]);
            }
        }
    }
}

// ================= k2: S-MMA + f16x2 sigmoid + PV-MMA =================
__global__ __launch_bounds__(128) void k2_aggregate(
    const float* __restrict__ temp_p,
    const float* __restrict__ theta_p)
{
    __shared__ __align__(16) __half sB[128 * XSTRIDE];
    __shared__ __align__(16) __half szh[128 * ZSTRIDE];
    __shared__ float stq[128];

    const int tid  = threadIdx.x;
    const int wid  = tid >> 5;
    const int lane = tid & 31;
    const int g = lane >> 2;
    const int t = lane & 3;

    const int rowBase = blockIdx.x * 128;
    const int jbase0  = blockIdx.y * JCHUNK;

    const float L2E  = 1.4426950408889634f;
    const float temp = *temp_p;
    const float thL  = (*theta_p) * L2E;
    const float pS   = 2.f * temp * L2E;

    uint32_t aih[2][4];
    float rc[2][2];
#pragma unroll
    for (int rg = 0; rg < 2; rg++) {
        int R  = rowBase + wid * 32 + rg * 16;
        int rA = R + g, rB = R + g + 8;
        aih[rg][0] = ld32g(g_zh + (size_t)rA * 16 + 2 * t);
        aih[rg][1] = ld32g(g_zh + (size_t)rB * 16 + 2 * t);
        aih[rg][2] = ld32g(g_zh + (size_t)rA * 16 + 2 * t + 8);
        aih[rg][3] = ld32g(g_zh + (size_t)rB * 16 + 2 * t + 8);
        rc[rg][0] = thL - g_tq[rA];
        rc[rg][1] = thL - g_tq[rB];
    }

    float C[2][8][4];
#pragma unroll
    for (int rg = 0; rg < 2; rg++)
#pragma unroll
        for (int nt = 0; nt < 8; nt++)
#pragma unroll
            for (int c = 0; c < 4; c++) C[rg][nt][c] = 0.f;

    const int lr = lane & 7;
    const int m4 = lane >> 3;
    const uint32_t pvBase = smem_u32(sB) +
        2 * (((m4 & 1) * 8 + lr) * XSTRIDE + (m4 >> 1) * 8);
    // x4 z-load map: lanes 0-7 -> m0 (rows +0, k 0-7), 8-15 -> m1 (rows +0, k 8-15),
    //                16-23 -> m2 (rows +8, k 0-7),     24-31 -> m3 (rows +8, k 8-15)
    const uint32_t zhBase = smem_u32(szh) +
        2 * (((lane & 7) + ((lane >> 4) << 3)) * ZSTRIDE + ((lane >> 3) & 1) * 8);

    for (int tl = 0; tl < TILES; ++tl) {
        const int jbase = jbase0 + tl * 128;
        __syncthreads();
        {
            const uint4* xs = (const uint4*)(g_x16 + (size_t)(jbase + tid) * 64);
            uint4* xd = (uint4*)(sB + tid * XSTRIDE);
#pragma unroll
            for (int q = 0; q < 8; q++) xd[q] = xs[q];
            const uint4* hs = (const uint4*)(g_zh + (size_t)(jbase + tid) * 16);
            uint4* hd = (uint4*)(szh + tid * ZSTRIDE);
            hd[0] = hs[0]; hd[1] = hs[1];
            stq[tid] = g_tq[jbase + tid];
        }
        __syncthreads();

        if (jbase == rowBase)
            k2_tile<true >(pvBase, zhBase, stq, aih, rc, pS, wid, g, t, C);
        else
            k2_tile<false>(pvBase, zhBase, stq, aih, rc, pS, wid, g, t, C);
    }

#pragma unroll
    for (int rg = 0; rg < 2; rg++) {
        int rA = rowBase + wid * 32 + rg * 16 + g;
        float* b0 = g_part + ((size_t)blockIdx.y * N + rA) * 64;
        float* b1 = b0 + (size_t)8 * 64;
#pragma unroll
        for (int nt = 0; nt < 8; nt++) {
            int col = nt * 8 + 2 * t;
            *(float2*)(b0 + col) = make_float2(C[rg][nt][0], C[rg][nt][1]);
            *(float2*)(b1 + col) = make_float2(C[rg][nt][2], C[rg][nt][3]);
        }
    }
}

// ================= k3: parallel reduce -> normalize -> fc3 -> fc6 -> softmax =================
// 512 thr/block, 8 threads per row, 64 rows/block, grid 128.
__global__ __launch_bounds__(512) void k3_head(
    const float* __restrict__ w3, const float* __restrict__ b3,
    const float* __restrict__ w6, const float* __restrict__ b6,
    float* __restrict__ out)
{
    __shared__ float sw3[8 * 64];   // padded: cols 60..63 = 0
    __shared__ float sb3[8], sw6[10 * 8], sb6[10];
    int tid = threadIdx.x;
    if (tid < 8 * 64) {
        int o = tid >> 6, k = tid & 63;
        sw3[tid] = (k < 60) ? w3[o * 60 + k] : 0.f;
    }
    if (tid < 8)  sb3[tid] = b3[tid];
    else if (tid >= 32 && tid < 112) sw6[tid - 32] = w6[tid - 32];
    else if (tid >= 128 && tid < 138) sb6[tid - 128] = b6[tid - 128];
    __syncthreads();

    const int rloc = tid >> 3, sub = tid & 7;
    const int r = blockIdx.x * 64 + rloc;

    float acc[8];
#pragma unroll
    for (int k = 0; k < 8; k++) acc[k] = 0.f;
#pragma unroll
    for (int s = 0; s < SPLIT; s++) {
        const float4* p = (const float4*)(g_part + ((size_t)s * N + r) * 64 + sub * 8);
        float4 v0 = p[0], v1 = p[1];
        acc[0] += v0.x; acc[1] += v0.y; acc[2] += v0.z; acc[3] += v0.w;
        acc[4] += v1.x; acc[5] += v1.y; acc[6] += v1.z; acc[7] += v1.w;
    }

    const unsigned fullm = 0xffffffffu;
    float rs = __shfl_sync(fullm, acc[4], (tid & 31) | 7);   // col 60
    float inv = 1.f / rs;
#pragma unroll
    for (int k = 0; k < 8; k++) acc[k] *= inv;

    float p8[8];
#pragma unroll
    for (int o = 0; o < 8; o++) {
        const float* wrow = sw3 + o * 64 + sub * 8;
        float s = 0.f;
#pragma unroll
        for (int k = 0; k < 8; k++) s = fmaf(wrow[k], acc[k], s);
        p8[o] = s;
    }
#pragma unroll
    for (int d = 1; d < 8; d <<= 1)
#pragma unroll
        for (int o = 0; o < 8; o++) p8[o] += __shfl_xor_sync(fullm, p8[o], d);

    float tv[8];
#pragma unroll
    for (int o = 0; o < 8; o++) tv[o] = p8[o] + sb3[o];

    float u[10];
    float m = -1e30f;
#pragma unroll
    for (int c = 0; c < 10; c++) {
        float s = sb6[c];
#pragma unroll
        for (int o = 0; o < 8; o++) s = fmaf(sw6[c * 8 + o], tv[o], s);
        u[c] = s;
        m = fmaxf(m, s);
    }
    float denom = 0.f;
#pragma unroll
    for (int c = 0; c < 10; c++) { u[c] = __expf(u[c] - m); denom += u[c]; }
    float dinv = 1.f / denom;
    if (sub == 0) {
#pragma unroll
        for (int c = 0; c < 10; c++) out[(size_t)r * 10 + c] = u[c] * dinv;
    }
}

// ================= launch =================
extern "C" void kernel_launch(void* const* d_in, const int* in_sizes, int n_in,
                              void* d_out, int out_size)
{
    const float* x     = (const float*)d_in[0];
    const float* w1    = (const float*)d_in[1];
    const float* b1    = (const float*)d_in[2];
    const float* w2    = (const float*)d_in[3];
    const float* b2    = (const float*)d_in[4];
    const float* w3    = (const float*)d_in[5];
    const float* b3    = (const float*)d_in[6];
    const float* w6    = (const float*)d_in[7];
    const float* b6    = (const float*)d_in[8];
    const float* temp  = (const float*)d_in[9];
    const float* theta = (const float*)d_in[10];
    float* out = (float*)d_out;

    k0_fold<<<1, 128>>>(w1, b1, w2, b2);
    k1_embed<<<N / 64, 256>>>(x, temp);
    dim3 g2(N / 128, SPLIT);
    k2_aggregate<<<g2, 128>>>(temp, theta);
    k3_head<<<N / 64, 512>>>(w3, b3, w6, b6, out);
}